// round 5
// baseline (speedup 1.0000x reference)
#include <cuda_runtime.h>
#include <math.h>

#define Bc   2
#define Cc   256
#define DMc  512
#define Hc   8
#define Dc   64
#define BHc  16
#define ROWS 4096   // B*H*C

typedef unsigned long long ULL;

// ---------------- f32x2 packed helpers ----------------
__device__ __forceinline__ void fma2(ULL& d, ULL a, ULL b) {
    asm("fma.rn.f32x2 %0, %1, %2, %0;" : "+l"(d) : "l"(a), "l"(b));
}
__device__ __forceinline__ ULL dup2(float x) {
    ULL d; asm("mov.b64 %0, {%1, %1};" : "=l"(d) : "f"(x)); return d;
}
__device__ __forceinline__ ULL pack2(float x, float y) {
    ULL d; asm("mov.b64 %0, {%1, %2};" : "=l"(d) : "f"(x), "f"(y)); return d;
}
__device__ __forceinline__ void unpack2(ULL v, float& x, float& y) {
    asm("mov.b64 {%0, %1}, %2;" : "=f"(x), "=f"(y) : "l"(v));
}

// Branchless gelu: A&S 7.1.26 erf (|err| <= 1.5e-7).
__device__ __forceinline__ float fast_gelu(float x) {
    float y  = x * 0.70710678118654752f;
    float ay = fabsf(y);
    float den = fmaf(0.3275911f, ay, 1.0f);
    float t;
    asm("rcp.approx.f32 %0, %1;" : "=f"(t) : "f"(den));
    float p = fmaf(1.061405429f, t, -1.453152027f);
    p = fmaf(p, t, 1.421413741f);
    p = fmaf(p, t, -0.284496736f);
    p = fmaf(p, t, 0.254829592f);
    p *= t;
    float e = __expf(-ay * ay);
    float erfv = fmaf(-p, e, 1.0f);
    erfv = copysignf(erfv, y);
    return 0.5f * x * (1.0f + erfv);
}

// ---------------- device scratch ----------------
__device__ float g_q [ROWS * Dc];
__device__ float g_k [ROWS * Dc];
__device__ float g_v [ROWS * Dc];
__device__ float g_ctx[Bc * Cc * DMc];

// =====================================================================
// GEMM: out[m,e] = sum_d A[m,d]*W[e,d] + bias[e]   (K = 512)
// =====================================================================
template<int TM>
__device__ __forceinline__ void gemm512(
    const float* __restrict__ A, const float* __restrict__ W,
    const float* __restrict__ bias, float* __restrict__ out, bool scatter,
    int m0, int n0)
{
    __shared__ float Xs[16][TM + 4];
    __shared__ float Wsh[16][68];
    constexpr int MT = TM / 16;
    int t  = threadIdx.x;
    int tx = t & 15, ty = t >> 4;
    int lr = t >> 2, kq = (t & 3) * 4;
    bool xload = (t < TM * 4);

    ULL acc[MT][2];
#pragma unroll
    for (int mm = 0; mm < MT; mm++) { acc[mm][0] = 0ULL; acc[mm][1] = 0ULL; }

    float4 xv, wv;
    if (xload) xv = *(const float4*)(A + (size_t)(m0 + lr) * 512 + kq);
    wv = *(const float4*)(W + (size_t)(n0 + lr) * 512 + kq);

    for (int kc = 0; kc < 512; kc += 16) {
        if (kc) __syncthreads();
        if (xload) {
            Xs[kq + 0][lr] = xv.x; Xs[kq + 1][lr] = xv.y;
            Xs[kq + 2][lr] = xv.z; Xs[kq + 3][lr] = xv.w;
        }
        Wsh[kq + 0][lr] = wv.x; Wsh[kq + 1][lr] = wv.y;
        Wsh[kq + 2][lr] = wv.z; Wsh[kq + 3][lr] = wv.w;
        __syncthreads();
        if (kc + 16 < 512) {
            if (xload) xv = *(const float4*)(A + (size_t)(m0 + lr) * 512 + kc + 16 + kq);
            wv = *(const float4*)(W + (size_t)(n0 + lr) * 512 + kc + 16 + kq);
        }
#pragma unroll
        for (int kk = 0; kk < 16; kk++) {
            ulonglong2 wb = *(const ulonglong2*)&Wsh[kk][tx * 4];
#pragma unroll
            for (int mm = 0; mm < MT; mm++) {
                ULL ad = dup2(Xs[kk][ty * MT + mm]);
                fma2(acc[mm][0], ad, wb.x);
                fma2(acc[mm][1], ad, wb.y);
            }
        }
    }

    int nb = n0 + tx * 4;
    float bb0 = bias[nb + 0], bb1 = bias[nb + 1];
    float bb2 = bias[nb + 2], bb3 = bias[nb + 3];
#pragma unroll
    for (int mm = 0; mm < MT; mm++) {
        int m = m0 + ty * MT + mm;
        float f0, f1, f2, f3;
        unpack2(acc[mm][0], f0, f1);
        unpack2(acc[mm][1], f2, f3);
        f0 += bb0; f1 += bb1; f2 += bb2; f3 += bb3;
        if (scatter) {
            int b = m >> 8, c = m & 255;
            int h = nb >> 6, d0 = nb & 63;
            *(float4*)(out + ((size_t)((b * 8 + h) * 256 + c)) * 64 + d0) =
                make_float4(f0, f1, f2, f3);
        } else {
            *(float4*)(out + (size_t)m * 512 + nb) = make_float4(f0, f1, f2, f3);
        }
    }
}

__global__ __launch_bounds__(256) void qkv_kernel(
    const float* __restrict__ x,
    const float* __restrict__ Wq, const float* __restrict__ bq,
    const float* __restrict__ Wk, const float* __restrict__ bk,
    const float* __restrict__ Wv, const float* __restrict__ bv)
{
    int z = blockIdx.z;
    const float* W = (z == 0) ? Wq : (z == 1) ? Wk : Wv;
    const float* b = (z == 0) ? bq : (z == 1) ? bk : bv;
    float* out     = (z == 0) ? g_q : (z == 1) ? g_k : g_v;
    gemm512<32>(x, W, b, out, true, blockIdx.y * 32, blockIdx.x * 64);
}

__global__ __launch_bounds__(256) void outproj_kernel(
    const float* __restrict__ Wo, const float* __restrict__ bo,
    float* __restrict__ out)
{
    gemm512<32>(g_ctx, Wo, bo, out, false, blockIdx.y * 32, blockIdx.x * 64);
}

// =====================================================================
// Main fused kernel. Block = (bh, 4 i's, one at a time), 256 threads,
// 2 CTAs/SM (smem 103.5KB, <=128 regs).
//   res[i,j,f] = sum_e K[j,e]*(q_i[e]*W3[f,e] + W1k[f,e]) + q_p[i,f] + b1[f]
// q_p computed inline; V read from global in the attn@V tail.
// =====================================================================
#define KS_O    0        // [64][260]  = 16640
#define W3LO_O  16640    // [64][36]
#define W3HI_O  18944    // [64][36]
#define ALO_O   21248    // [64][36]
#define AHI_O   23552    // [64][36]
#define QROW_O  25856    // [64]
#define SC_O    25920    // [256]
#define RED_O   26176    // [64]
#define PART_O  26240    // [256]
#define SMEM_FLOATS 26496
#define SMEM_BYTES  (SMEM_FLOATS * 4)

__global__ __launch_bounds__(256, 2) void main_kernel(
    const float* __restrict__ w1, const float* __restrict__ b1,
    const float* __restrict__ w2, const float* __restrict__ b2)
{
    extern __shared__ float sm[];
    int t  = threadIdx.x;
    int bh = blockIdx.y;
    int i0 = blockIdx.x * 4;
    int base = bh * 256;
    int jg = t >> 3, fg = t & 7;

    float w2r[8];
#pragma unroll
    for (int ff = 0; ff < 8; ff++) w2r[ff] = __ldg(&w2[fg * 8 + ff]);
    float b2v = __ldg(&b2[0]);

    // ---- stage K transposed: sm_K[e][j], stride 260 ----
#pragma unroll
    for (int it = 0; it < 16; it++) {
        int task = t + it * 256;
        int eg = task & 15, j = task >> 4;
        float4 kv = *(const float4*)(g_k + (size_t)(base + j) * 64 + eg * 4);
        sm[KS_O + (eg * 4 + 0) * 260 + j] = kv.x;
        sm[KS_O + (eg * 4 + 1) * 260 + j] = kv.y;
        sm[KS_O + (eg * 4 + 2) * 260 + j] = kv.z;
        sm[KS_O + (eg * 4 + 3) * 260 + j] = kv.w;
    }

    // ---- stage W3 split (e-coalesced column mapping) ----
    // thread -> (half, pos) = col within split, e-chunk of 16
    int col6 = t & 63;
    int e0c  = (t >> 6) * 16;
    int half = col6 >> 5;
    int pos  = col6 & 31;
    int fcol = (pos >> 2) * 8 + half * 4 + (pos & 3);   // actual f
    {
        const float* w3g = w1 + (size_t)fcol * 192 + 128;
        float* W3 = sm + (half ? W3HI_O : W3LO_O);
#pragma unroll
        for (int e = 0; e < 16; e++)
            W3[(e0c + e) * 36 + pos] = w3g[e0c + e];
    }

    const float* w1kg = w1 + (size_t)fcol * 192 + 64;
    const float* w1qg = w1 + (size_t)(t & 63) * 192 + (t >> 6) * 16;

#pragma unroll 1
    for (int ip = 0; ip < 4; ip++) {
        int i = i0 + ip;
        __syncthreads();   // K/W3 ready (1st) / previous-i consumers done

        if (t < 16) {
            float4 qv = *(const float4*)(g_q + (size_t)(base + i) * 64 + t * 4);
            *(float4*)&sm[QROW_O + t * 4] = qv;
        }
        __syncthreads();

        // ---- build A'[e][col] = qrow[e]*W3[e][col] + w1k[f][e]  (split) ----
        {
            const float* W3 = sm + (half ? W3HI_O : W3LO_O);
            float* A = sm + (half ? AHI_O : ALO_O);
#pragma unroll
            for (int e = 0; e < 16; e++) {
                int ee = e0c + e;
                A[ee * 36 + pos] = fmaf(sm[QROW_O + ee], W3[ee * 36 + pos], w1kg[ee]);
            }
            // q_p partial: part[quarter*64 + f] = sum over 16 d
            float s = 0.f;
            const float* qr = sm + QROW_O + (t >> 6) * 16;
#pragma unroll
            for (int d = 0; d < 16; d++) s = fmaf(qr[d], w1qg[d], s);
            sm[PART_O + t] = s;
        }
        __syncthreads();

        // ---- acc init = q_p + b1 at f = fg*8 + ff ----
        ULL acc[8][4];
        {
            float qpb[8];
            float4 b1a = *(const float4*)(b1 + fg * 8);
            float4 b1b = *(const float4*)(b1 + fg * 8 + 4);
            float bb[8] = {b1a.x, b1a.y, b1a.z, b1a.w, b1b.x, b1b.y, b1b.z, b1b.w};
#pragma unroll
            for (int ff = 0; ff < 8; ff++) {
                int f = fg * 8 + ff;
                qpb[ff] = sm[PART_O + f] + sm[PART_O + 64 + f] +
                          sm[PART_O + 128 + f] + sm[PART_O + 192 + f] + bb[ff];
            }
            ULL c0 = pack2(qpb[0], qpb[1]);
            ULL c1 = pack2(qpb[2], qpb[3]);
            ULL c2 = pack2(qpb[4], qpb[5]);
            ULL c3 = pack2(qpb[6], qpb[7]);
#pragma unroll
            for (int jj = 0; jj < 8; jj++) {
                acc[jj][0] = c0; acc[jj][1] = c1;
                acc[jj][2] = c2; acc[jj][3] = c3;
            }
        }

        // ---- GEMM: res[j,f] += sum_e K[j,e]*A'[e,f] ----
#pragma unroll 2
        for (int e = 0; e < 64; e++) {
            float4 k0 = *(const float4*)&sm[KS_O + e * 260 + jg * 8];
            float4 k1 = *(const float4*)&sm[KS_O + e * 260 + jg * 8 + 4];
            ulonglong2 al = *(const ulonglong2*)&sm[ALO_O + e * 36 + fg * 4];
            ulonglong2 ah = *(const ulonglong2*)&sm[AHI_O + e * 36 + fg * 4];
            float kv[8] = {k0.x, k0.y, k0.z, k0.w, k1.x, k1.y, k1.z, k1.w};
#pragma unroll
            for (int jj = 0; jj < 8; jj++) {
                ULL kd = dup2(kv[jj]);
                fma2(acc[jj][0], kd, al.x);
                fma2(acc[jj][1], kd, al.y);
                fma2(acc[jj][2], kd, ah.x);
                fma2(acc[jj][3], kd, ah.y);
            }
        }

        // ---- epilogue: sc[j] = (sum_f gelu(res)*w2[f] + b2) / 8 ----
#pragma unroll
        for (int jj = 0; jj < 8; jj++) {
            int j = jg * 8 + jj;
            float r0, r1, r2, r3, r4, r5, r6, r7;
            unpack2(acc[jj][0], r0, r1);
            unpack2(acc[jj][1], r2, r3);
            unpack2(acc[jj][2], r4, r5);
            unpack2(acc[jj][3], r6, r7);
            float s = 0.f;
            s = fmaf(fast_gelu(r0), w2r[0], s);
            s = fmaf(fast_gelu(r1), w2r[1], s);
            s = fmaf(fast_gelu(r2), w2r[2], s);
            s = fmaf(fast_gelu(r3), w2r[3], s);
            s = fmaf(fast_gelu(r4), w2r[4], s);
            s = fmaf(fast_gelu(r5), w2r[5], s);
            s = fmaf(fast_gelu(r6), w2r[6], s);
            s = fmaf(fast_gelu(r7), w2r[7], s);
            s += __shfl_xor_sync(0xffffffffu, s, 1);
            s += __shfl_xor_sync(0xffffffffu, s, 2);
            s += __shfl_xor_sync(0xffffffffu, s, 4);
            if (fg == 0) sm[SC_O + j] = (s + b2v) * 0.125f;
        }
        __syncthreads();

        // ---- top-64 threshold, softmax ----
        float v = sm[SC_O + t];
        float m = v;
#pragma unroll
        for (int o = 16; o; o >>= 1)
            m = fmaxf(m, __shfl_xor_sync(0xffffffffu, m, o));
        if ((t & 31) == 0) sm[RED_O + (t >> 5)] = m;
        __syncthreads();
        float mx = sm[RED_O];
#pragma unroll
        for (int w = 1; w < 8; w++) mx = fmaxf(mx, sm[RED_O + w]);

        int cg = 0, ce = 0;
        const float* scp = sm + SC_O;
#pragma unroll 8
        for (int jt = 0; jt < 64; jt++) {
            float4 a = *(const float4*)(scp + jt * 4);
            cg += (a.x > v) + (a.y > v) + (a.z > v) + (a.w > v);
            ce += (a.x == v) + (a.y == v) + (a.z == v) + (a.w == v);
        }
        if (cg <= 63 && cg + ce >= 64) sm[RED_O + 8] = v;
        __syncthreads();
        float thr = sm[RED_O + 8];

        float ev = (v >= thr) ? __expf(v - mx) : 0.f;
        float ssum = ev;
#pragma unroll
        for (int o = 16; o; o >>= 1)
            ssum += __shfl_xor_sync(0xffffffffu, ssum, o);
        if ((t & 31) == 0) sm[RED_O + 16 + (t >> 5)] = ssum;
        __syncthreads();
        float den = 0.f;
#pragma unroll
        for (int w = 0; w < 8; w++) den += sm[RED_O + 16 + w];
        sm[SC_O + t] = ev / den;
        __syncthreads();

        // ---- attn @ V (V from global, L2-resident) ----
        {
            int g = t >> 6, d = t & 63;
            float a = 0.f;
            const float* ap = sm + SC_O + g * 64;
            const float* vg = g_v + (size_t)(base + g * 64) * 64 + d;
#pragma unroll 4
            for (int j = 0; j < 64; j++)
                a = fmaf(ap[j], vg[(size_t)j * 64], a);
            sm[PART_O + t] = a;
        }
        __syncthreads();
        if (t < 64) {
            float o = sm[PART_O + t] + sm[PART_O + 64 + t] +
                      sm[PART_O + 128 + t] + sm[PART_O + 192 + t];
            g_ctx[(size_t)((bh >> 3) * 256 + i) * 512 + (bh & 7) * 64 + t] = o;
        }
    }
}

// =====================================================================
extern "C" void kernel_launch(void* const* d_in, const int* in_sizes, int n_in,
                              void* d_out, int out_size)
{
    const float* x  = (const float*)d_in[0];
    const float* Wq = (const float*)d_in[1];
    const float* bq = (const float*)d_in[2];
    const float* Wk = (const float*)d_in[3];
    const float* bk = (const float*)d_in[4];
    const float* Wv = (const float*)d_in[5];
    const float* bv = (const float*)d_in[6];
    const float* w1 = (const float*)d_in[7];
    const float* b1 = (const float*)d_in[8];
    const float* w2 = (const float*)d_in[9];
    const float* b2 = (const float*)d_in[10];
    const float* Wo = (const float*)d_in[11];
    const float* bo = (const float*)d_in[12];
    float* out = (float*)d_out;

    cudaFuncSetAttribute(main_kernel,
                         cudaFuncAttributeMaxDynamicSharedMemorySize, SMEM_BYTES);

    qkv_kernel<<<dim3(8, 16, 3), 256>>>(x, Wq, bq, Wk, bk, Wv, bv);
    main_kernel<<<dim3(64, 16), 256, SMEM_BYTES>>>(w1, b1, w2, b2);
    outproj_kernel<<<dim3(8, 16), 256>>>(Wo, bo, out);
}